// round 2
// baseline (speedup 1.0000x reference)
#include <cuda_runtime.h>
#include <cstdint>

#define DT_F      0.1f
#define NITERS    9               // int(1.0 // 0.1) == 9 in Python float semantics!
#define BATCH     64
#define NN        1024
#define NOBS      64
#define NACT      16
#define GROUPS    4
#define CPB       32              // CTAs per batch
#define NROWS     32              // rows per CTA
#define BPG       (BATCH / GROUPS)
#define NTHREADS  256

// y-exchange buffer: 8-byte words = (tag<<32) | float_bits. Double buffered by iter parity.
__device__ unsigned long long g_ybuf[2][BATCH][NN];

__device__ __forceinline__ unsigned long long ldcg64(const unsigned long long* p) {
    unsigned long long v;
    asm volatile("ld.global.cg.u64 %0, [%1];" : "=l"(v) : "l"(p));
    return v;
}
__device__ __forceinline__ void stcg64(unsigned long long* p, unsigned long long v) {
    asm volatile("st.global.cg.u64 [%0], %1;" :: "l"(p), "l"(v) : "memory");
}
__device__ __forceinline__ void cp_async16(void* smem, const void* gmem) {
    unsigned s = (unsigned)__cvta_generic_to_shared(smem);
    asm volatile("cp.async.cg.shared.global [%0], [%1], 16;" :: "r"(s), "l"(gmem));
}

__global__ void ctrnn_init_kernel() {
    int idx = blockIdx.x * blockDim.x + threadIdx.x;
    if (idx < 2 * BATCH * NN)
        ((unsigned long long*)g_ybuf)[idx] = 0ull;
}

// SMEM layout (dynamic):
//   float4 Ws[NROWS * NN/4]          : 131072 B   (this CTA's 32 rows of W[b])
//   float  y_s[NN]                   : 4096 B
//   float  v_s,a_s,I_s,gain_s,bias_s,mask_s [NROWS each]
//   float  obs_s[NOBS], red_s[8]
#define SMEM_FLOATS (NROWS * NN + NN + 6 * NROWS + NOBS + 8)
#define SMEM_BYTES  (SMEM_FLOATS * 4)

__global__ __launch_bounds__(NTHREADS, 1)
void ctrnn_kernel(const float* __restrict__ obs,  const float* __restrict__ v0,
                  const float* __restrict__ tau,  const float* __restrict__ gain,
                  const float* __restrict__ bias, const float* __restrict__ W,
                  const float* __restrict__ mask, const float* __restrict__ E,
                  const float* __restrict__ D,    float* __restrict__ out)
{
    extern __shared__ float4 sm4[];
    float4* Ws     = sm4;                              // 8192 float4
    float*  y_s    = (float*)(Ws + NROWS * (NN / 4));  // 1024
    float*  v_s    = y_s    + NN;
    float*  a_s    = v_s    + NROWS;
    float*  I_s    = a_s    + NROWS;
    float*  gain_s = I_s    + NROWS;
    float*  bias_s = gain_s + NROWS;
    float*  mask_s = bias_s + NROWS;
    float*  obs_s  = mask_s + NROWS;                   // 64
    float*  red_s  = obs_s  + NOBS;                    // 8

    const int tid  = threadIdx.x;
    const int warp = tid >> 5;
    const int lane = tid & 31;
    const int group = blockIdx.x >> 5;   // blockIdx / CPB
    const int cig   = blockIdx.x & 31;   // CTA index within group
    const int base  = cig * NROWS;       // first row owned by this CTA

    for (int bi = 0; bi < BPG; bi++) {
        const int b = group * BPG + bi;

        // ---- async-load this CTA's W chunk (32 contiguous rows) into SMEM ----
        const float4* Wg = (const float4*)(W + ((size_t)b * NN + base) * NN);
        #pragma unroll 4
        for (int i = tid; i < NROWS * (NN / 4); i += NTHREADS)
            cp_async16(&Ws[i], &Wg[i]);
        asm volatile("cp.async.commit_group;");

        // ---- prologue overlapped with the copy ----
        if (tid < NOBS) obs_s[tid] = obs[(size_t)b * NOBS + tid];

        const float* vg = v0   + (size_t)b * NN;
        const float* gg = gain + (size_t)b * NN;
        const float* bg = bias + (size_t)b * NN;
        const float* mg = mask + (size_t)b * NN;

        // y0 for the FULL batch, computed locally (avoids first exchange)
        for (int i = tid; i < NN; i += NTHREADS)
            y_s[i] = tanhf(gg[i] * (vg[i] + bg[i])) * mg[i];
        __syncthreads();  // obs_s ready

        if (tid < NROWS) {
            int n = base + tid;
            v_s[tid]    = vg[n];
            a_s[tid]    = DT_F / tau[(size_t)b * NN + n];
            gain_s[tid] = gg[n];
            bias_s[tid] = bg[n];
            mask_s[tid] = mg[n];
            const float* Er = E + ((size_t)b * NN + n) * NOBS;
            float s = 0.f;
            #pragma unroll
            for (int o = 0; o < NOBS; o++) s += Er[o] * obs_s[o];
            I_s[tid] = s;
        }
        asm volatile("cp.async.wait_group 0;");
        __syncthreads();

        const float4* Y4 = (const float4*)y_s;

        for (int t = 1; t <= NITERS; t++) {
            if (t > 1) {
                // gather y_{t-1} from all CTAs of this batch (tag-polled)
                const unsigned long long* src = &g_ybuf[(t - 1) & 1][b][0];
                const unsigned exp = (unsigned)(t - 1);
                for (int i = tid; i < NN; i += NTHREADS) {
                    unsigned long long v = ldcg64(src + i);
                    while ((unsigned)(v >> 32) != exp) {
                        __nanosleep(40);
                        v = ldcg64(src + i);
                    }
                    y_s[i] = __uint_as_float((unsigned)(v & 0xffffffffu));
                }
                __syncthreads();
            }

            // ---- 4 rows per warp: dot(W_row, y) from SMEM ----
            float acc0 = 0.f, acc1 = 0.f, acc2 = 0.f, acc3 = 0.f;
            const float4* W0 = Ws + (size_t)(warp * 4 + 0) * (NN / 4);
            const float4* W1 = W0 + (NN / 4);
            const float4* W2 = W1 + (NN / 4);
            const float4* W3 = W2 + (NN / 4);
            #pragma unroll
            for (int k = 0; k < 8; k++) {
                int c = k * 32 + lane;
                float4 y4 = Y4[c];
                float4 a;
                a = W0[c]; acc0 += a.x*y4.x; acc0 += a.y*y4.y; acc0 += a.z*y4.z; acc0 += a.w*y4.w;
                a = W1[c]; acc1 += a.x*y4.x; acc1 += a.y*y4.y; acc1 += a.z*y4.z; acc1 += a.w*y4.w;
                a = W2[c]; acc2 += a.x*y4.x; acc2 += a.y*y4.y; acc2 += a.z*y4.z; acc2 += a.w*y4.w;
                a = W3[c]; acc3 += a.x*y4.x; acc3 += a.y*y4.y; acc3 += a.z*y4.z; acc3 += a.w*y4.w;
            }
            #pragma unroll
            for (int off = 16; off > 0; off >>= 1) {
                acc0 += __shfl_xor_sync(0xffffffffu, acc0, off);
                acc1 += __shfl_xor_sync(0xffffffffu, acc1, off);
                acc2 += __shfl_xor_sync(0xffffffffu, acc2, off);
                acc3 += __shfl_xor_sync(0xffffffffu, acc3, off);
            }

            if (lane < 4) {
                float dot = (lane == 0) ? acc0 : (lane == 1) ? acc1 : (lane == 2) ? acc2 : acc3;
                int r = warp * 4 + lane;
                float v  = v_s[r];
                float nv = (v + a_s[r] * (dot + I_s[r] - v)) * mask_s[r];
                v_s[r] = nv;
                // publish y_t (or final v at t==NITERS) with tag t
                float ov = (t < NITERS) ? tanhf(gain_s[r] * (nv + bias_s[r])) * mask_s[r] : nv;
                unsigned long long pk =
                    ((unsigned long long)(unsigned)t << 32) |
                    (unsigned long long)__float_as_uint(ov);
                stcg64(&g_ybuf[t & 1][b][base + r], pk);
            }
            __syncthreads();
        }

        // ---- decode: CTAs 0..15 each produce one action ----
        if (cig < NACT) {
            const unsigned long long* src = &g_ybuf[NITERS & 1][b][0];
            for (int i = tid; i < NN; i += NTHREADS) {
                unsigned long long v = ldcg64(src + i);
                while ((unsigned)(v >> 32) != (unsigned)NITERS) {
                    __nanosleep(40);
                    v = ldcg64(src + i);
                }
                y_s[i] = __uint_as_float((unsigned)(v & 0xffffffffu));
            }
            __syncthreads();
            const float* Dr = D + ((size_t)b * NACT + cig) * NN;
            float p = 0.f;
            for (int i = tid; i < NN; i += NTHREADS) p += Dr[i] * y_s[i];
            #pragma unroll
            for (int off = 16; off > 0; off >>= 1)
                p += __shfl_xor_sync(0xffffffffu, p, off);
            if (lane == 0) red_s[warp] = p;
            __syncthreads();
            if (tid == 0) {
                float s = 0.f;
                #pragma unroll
                for (int j = 0; j < 8; j++) s += red_s[j];
                out[b * NACT + cig] = s;
            }
            __syncthreads();
        }
        __syncthreads();  // before next batch reuses SMEM
    }
}

extern "C" void kernel_launch(void* const* d_in, const int* in_sizes, int n_in,
                              void* d_out, int out_size) {
    const float* obs  = (const float*)d_in[0];
    const float* v0   = (const float*)d_in[1];
    const float* tau  = (const float*)d_in[2];
    const float* gain = (const float*)d_in[3];
    const float* bias = (const float*)d_in[4];
    const float* W    = (const float*)d_in[5];
    const float* mask = (const float*)d_in[6];
    const float* E    = (const float*)d_in[7];
    const float* D    = (const float*)d_in[8];
    float* out = (float*)d_out;

    cudaFuncSetAttribute(ctrnn_kernel,
                         cudaFuncAttributeMaxDynamicSharedMemorySize, SMEM_BYTES);

    // reset exchange tags each launch (graph-replay safe, deterministic)
    ctrnn_init_kernel<<<(2 * BATCH * NN + 255) / 256, 256>>>();

    // 128 CTAs, 136 KB smem each -> 1 CTA/SM, all co-resident on 148 SMs
    ctrnn_kernel<<<GROUPS * CPB, NTHREADS, SMEM_BYTES>>>(
        obs, v0, tau, gain, bias, W, mask, E, D, out);
}

// round 3
// speedup vs baseline: 1.3691x; 1.3691x over previous
#include <cuda_runtime.h>
#include <cstdint>

#define DT_F      0.1f
#define NITERS    9               // int(1.0 // 0.1) == 9 in Python float semantics!
#define BATCH     64
#define NN        1024
#define NOBS      64
#define NACT      16
#define GROUPS    4
#define CPB       32              // CTAs per batch
#define NROWS     32              // rows per CTA
#define BPG       (BATCH / GROUPS)
#define NTHREADS  256

// y-exchange buffer: 8-byte words = (tag<<32) | float_bits. Double buffered by iter parity.
__device__ unsigned long long g_ybuf[2][BATCH][NN];

__device__ __forceinline__ unsigned long long ldcg64(const unsigned long long* p) {
    unsigned long long v;
    asm volatile("ld.global.cg.u64 %0, [%1];" : "=l"(v) : "l"(p));
    return v;
}
__device__ __forceinline__ void stcg64(unsigned long long* p, unsigned long long v) {
    asm volatile("st.global.cg.u64 [%0], %1;" :: "l"(p), "l"(v) : "memory");
}

__global__ void ctrnn_init_kernel() {
    int idx = blockIdx.x * blockDim.x + threadIdx.x;
    if (idx < 2 * BATCH * NN)
        ((unsigned long long*)g_ybuf)[idx] = 0ull;
}

// SMEM layout (dynamic, 16B-aligned base):
//   float4 Ws[NROWS*NN/4]  : 131072 B  (TMA staging for NEXT batch's W chunk)
//   float  y_s[NN]         : 4096 B
//   float  v_s,a_s,I_s,gain_s,bias_s,mask_s [NROWS each]
//   float  obs_s[NOBS], red_s[8]
//   u64    mbar
#define SMEM_FLOATS (NROWS * NN + NN + 6 * NROWS + NOBS + 8 + 4)
#define SMEM_BYTES  (SMEM_FLOATS * 4)

__device__ __forceinline__ void mbar_init(uint32_t a, uint32_t cnt) {
    asm volatile("mbarrier.init.shared.b64 [%0], %1;" :: "r"(a), "r"(cnt) : "memory");
}
__device__ __forceinline__ void mbar_expect_tx(uint32_t a, uint32_t bytes) {
    asm volatile("mbarrier.arrive.expect_tx.shared.b64 _, [%0], %1;" :: "r"(a), "r"(bytes) : "memory");
}
__device__ __forceinline__ void mbar_wait(uint32_t a, uint32_t parity) {
    asm volatile(
        "{\n\t.reg .pred P;\n\t"
        "W_%=:\n\t"
        "mbarrier.try_wait.parity.shared.b64 P, [%0], %1;\n\t"
        "@P bra.uni D_%=;\n\t"
        "bra.uni W_%=;\n\t"
        "D_%=:\n\t}"
        :: "r"(a), "r"(parity) : "memory");
}
__device__ __forceinline__ void bulk_g2s(uint32_t dst, const void* src, uint32_t bytes, uint32_t mbar) {
    asm volatile(
        "cp.async.bulk.shared::cta.global.mbarrier::complete_tx::bytes [%0], [%1], %2, [%3];"
        :: "r"(dst), "l"(src), "r"(bytes), "r"(mbar) : "memory");
}

__global__ __launch_bounds__(NTHREADS, 1)
void ctrnn_kernel(const float* __restrict__ obs,  const float* __restrict__ v0,
                  const float* __restrict__ tau,  const float* __restrict__ gain,
                  const float* __restrict__ bias, const float* __restrict__ W,
                  const float* __restrict__ mask, const float* __restrict__ E,
                  const float* __restrict__ D,    float* __restrict__ out)
{
    extern __shared__ float4 sm4[];
    float4* Ws     = sm4;                              // 8192 float4 (staging)
    float*  y_s    = (float*)(Ws + NROWS * (NN / 4));  // 1024
    float*  v_s    = y_s    + NN;
    float*  a_s    = v_s    + NROWS;
    float*  I_s    = a_s    + NROWS;
    float*  gain_s = I_s    + NROWS;
    float*  bias_s = gain_s + NROWS;
    float*  mask_s = bias_s + NROWS;
    float*  obs_s  = mask_s + NROWS;                   // 64
    float*  red_s  = obs_s  + NOBS;                    // 8
    unsigned long long* mbar64 = (unsigned long long*)(red_s + 8);

    const int tid  = threadIdx.x;
    const int warp = tid >> 5;
    const int lane = tid & 31;
    const int group = blockIdx.x >> 5;   // blockIdx / CPB
    const int cig   = blockIdx.x & 31;   // CTA index within group
    const int base  = cig * NROWS;       // first row owned by this CTA

    const uint32_t mbar = (uint32_t)__cvta_generic_to_shared(mbar64);
    const uint32_t WsAddr = (uint32_t)__cvta_generic_to_shared(Ws);

    // ---- kick off TMA for batch 0's W chunk ----
    if (tid == 0) {
        mbar_init(mbar, 1);
        asm volatile("fence.proxy.async.shared::cta;" ::: "memory");
        mbar_expect_tx(mbar, NROWS * NN * 4);
        const char* src0 = (const char*)(W + ((size_t)(group * BPG) * NN + base) * NN);
        #pragma unroll
        for (int c = 0; c < 4; c++)
            bulk_g2s(WsAddr + c * 32768, src0 + c * 32768, 32768, mbar);
    }
    __syncthreads();

    float4 Wreg[4][8];   // 4 rows x 8 float4 (lane owns k-float4 indices lane+32j)

    for (int bi = 0; bi < BPG; bi++) {
        const int b = group * BPG + bi;

        // ---- wait for this batch's W, copy SMEM -> registers ----
        mbar_wait(mbar, (uint32_t)(bi & 1));
        {
            const float4* Wrow0 = Ws + (size_t)(warp * 4) * (NN / 4);
            #pragma unroll
            for (int r = 0; r < 4; r++)
                #pragma unroll
                for (int j = 0; j < 8; j++)
                    Wreg[r][j] = Wrow0[r * (NN / 4) + j * 32 + lane];
        }
        __syncthreads();

        // ---- issue TMA for NEXT batch's W into the (now free) staging buffer ----
        if (tid == 0 && bi + 1 < BPG) {
            mbar_expect_tx(mbar, NROWS * NN * 4);
            const char* srcn = (const char*)(W + ((size_t)(b + 1) * NN + base) * NN);
            #pragma unroll
            for (int c = 0; c < 4; c++)
                bulk_g2s(WsAddr + c * 32768, srcn + c * 32768, 32768, mbar);
        }

        // ---- prologue ----
        if (tid < NOBS) obs_s[tid] = obs[(size_t)b * NOBS + tid];

        const float* vg = v0   + (size_t)b * NN;
        const float* gg = gain + (size_t)b * NN;
        const float* bg = bias + (size_t)b * NN;
        const float* mg = mask + (size_t)b * NN;

        // y0 for the FULL batch, computed locally (avoids first exchange)
        for (int i = tid; i < NN; i += NTHREADS)
            y_s[i] = tanhf(gg[i] * (vg[i] + bg[i])) * mg[i];
        __syncthreads();  // obs_s ready

        if (tid < NROWS) {
            int n = base + tid;
            v_s[tid]    = vg[n];
            a_s[tid]    = DT_F / tau[(size_t)b * NN + n];
            gain_s[tid] = gg[n];
            bias_s[tid] = bg[n];
            mask_s[tid] = mg[n];
            const float* Er = E + ((size_t)b * NN + n) * NOBS;
            float s = 0.f;
            #pragma unroll
            for (int o = 0; o < NOBS; o++) s += Er[o] * obs_s[o];
            I_s[tid] = s;
        }
        __syncthreads();

        const float4* Y4 = (const float4*)y_s;

        for (int t = 1; t <= NITERS; t++) {
            if (t > 1) {
                // gather y_{t-1} from all CTAs of this batch (tag-polled, MLP=4)
                const unsigned long long* src = &g_ybuf[(t - 1) & 1][b][0];
                const unsigned exp = (unsigned)(t - 1);
                unsigned long long v0w, v1w, v2w, v3w;
                v0w = ldcg64(src + tid);
                v1w = ldcg64(src + tid + 256);
                v2w = ldcg64(src + tid + 512);
                v3w = ldcg64(src + tid + 768);
                while ((unsigned)(v0w >> 32) != exp) { __nanosleep(20); v0w = ldcg64(src + tid); }
                while ((unsigned)(v1w >> 32) != exp) { __nanosleep(20); v1w = ldcg64(src + tid + 256); }
                while ((unsigned)(v2w >> 32) != exp) { __nanosleep(20); v2w = ldcg64(src + tid + 512); }
                while ((unsigned)(v3w >> 32) != exp) { __nanosleep(20); v3w = ldcg64(src + tid + 768); }
                y_s[tid]       = __uint_as_float((unsigned)(v0w & 0xffffffffu));
                y_s[tid + 256] = __uint_as_float((unsigned)(v1w & 0xffffffffu));
                y_s[tid + 512] = __uint_as_float((unsigned)(v2w & 0xffffffffu));
                y_s[tid + 768] = __uint_as_float((unsigned)(v3w & 0xffffffffu));
                __syncthreads();
            }

            // ---- 4 rows per warp: dot(W_row, y) from REGISTERS ----
            float acc0 = 0.f, acc1 = 0.f, acc2 = 0.f, acc3 = 0.f;
            #pragma unroll
            for (int j = 0; j < 8; j++) {
                float4 y4 = Y4[j * 32 + lane];
                float4 a;
                a = Wreg[0][j]; acc0 += a.x*y4.x; acc0 += a.y*y4.y; acc0 += a.z*y4.z; acc0 += a.w*y4.w;
                a = Wreg[1][j]; acc1 += a.x*y4.x; acc1 += a.y*y4.y; acc1 += a.z*y4.z; acc1 += a.w*y4.w;
                a = Wreg[2][j]; acc2 += a.x*y4.x; acc2 += a.y*y4.y; acc2 += a.z*y4.z; acc2 += a.w*y4.w;
                a = Wreg[3][j]; acc3 += a.x*y4.x; acc3 += a.y*y4.y; acc3 += a.z*y4.z; acc3 += a.w*y4.w;
            }
            #pragma unroll
            for (int off = 16; off > 0; off >>= 1) {
                acc0 += __shfl_xor_sync(0xffffffffu, acc0, off);
                acc1 += __shfl_xor_sync(0xffffffffu, acc1, off);
                acc2 += __shfl_xor_sync(0xffffffffu, acc2, off);
                acc3 += __shfl_xor_sync(0xffffffffu, acc3, off);
            }

            if (lane < 4) {
                float dot = (lane == 0) ? acc0 : (lane == 1) ? acc1 : (lane == 2) ? acc2 : acc3;
                int r = warp * 4 + lane;
                float v  = v_s[r];
                float nv = (v + a_s[r] * (dot + I_s[r] - v)) * mask_s[r];
                v_s[r] = nv;
                // publish y_t (or final v at t==NITERS) with tag t
                float ov = (t < NITERS) ? tanhf(gain_s[r] * (nv + bias_s[r])) * mask_s[r] : nv;
                unsigned long long pk =
                    ((unsigned long long)(unsigned)t << 32) |
                    (unsigned long long)__float_as_uint(ov);
                stcg64(&g_ybuf[t & 1][b][base + r], pk);
            }
            __syncthreads();
        }

        // ---- decode: CTAs 0..15 each produce one action ----
        if (cig < NACT) {
            const unsigned long long* src = &g_ybuf[NITERS & 1][b][0];
            unsigned long long v0w, v1w, v2w, v3w;
            v0w = ldcg64(src + tid);
            v1w = ldcg64(src + tid + 256);
            v2w = ldcg64(src + tid + 512);
            v3w = ldcg64(src + tid + 768);
            const unsigned expf = (unsigned)NITERS;
            while ((unsigned)(v0w >> 32) != expf) { __nanosleep(20); v0w = ldcg64(src + tid); }
            while ((unsigned)(v1w >> 32) != expf) { __nanosleep(20); v1w = ldcg64(src + tid + 256); }
            while ((unsigned)(v2w >> 32) != expf) { __nanosleep(20); v2w = ldcg64(src + tid + 512); }
            while ((unsigned)(v3w >> 32) != expf) { __nanosleep(20); v3w = ldcg64(src + tid + 768); }
            y_s[tid]       = __uint_as_float((unsigned)(v0w & 0xffffffffu));
            y_s[tid + 256] = __uint_as_float((unsigned)(v1w & 0xffffffffu));
            y_s[tid + 512] = __uint_as_float((unsigned)(v2w & 0xffffffffu));
            y_s[tid + 768] = __uint_as_float((unsigned)(v3w & 0xffffffffu));
            __syncthreads();
            const float* Dr = D + ((size_t)b * NACT + cig) * NN;
            float p = 0.f;
            for (int i = tid; i < NN; i += NTHREADS) p += Dr[i] * y_s[i];
            #pragma unroll
            for (int off = 16; off > 0; off >>= 1)
                p += __shfl_xor_sync(0xffffffffu, p, off);
            if (lane == 0) red_s[warp] = p;
            __syncthreads();
            if (tid == 0) {
                float s = 0.f;
                #pragma unroll
                for (int j = 0; j < 8; j++) s += red_s[j];
                out[b * NACT + cig] = s;
            }
            __syncthreads();
        }
        __syncthreads();  // before next batch reuses y_s / params
    }
}

extern "C" void kernel_launch(void* const* d_in, const int* in_sizes, int n_in,
                              void* d_out, int out_size) {
    const float* obs  = (const float*)d_in[0];
    const float* v0   = (const float*)d_in[1];
    const float* tau  = (const float*)d_in[2];
    const float* gain = (const float*)d_in[3];
    const float* bias = (const float*)d_in[4];
    const float* W    = (const float*)d_in[5];
    const float* mask = (const float*)d_in[6];
    const float* E    = (const float*)d_in[7];
    const float* D    = (const float*)d_in[8];
    float* out = (float*)d_out;

    cudaFuncSetAttribute(ctrnn_kernel,
                         cudaFuncAttributeMaxDynamicSharedMemorySize, SMEM_BYTES);

    // reset exchange tags each launch (graph-replay safe, deterministic)
    ctrnn_init_kernel<<<(2 * BATCH * NN + 255) / 256, 256>>>();

    // 128 CTAs, ~136 KB smem each -> 1 CTA/SM, all co-resident on 148 SMs
    ctrnn_kernel<<<GROUPS * CPB, NTHREADS, SMEM_BYTES>>>(
        obs, v0, tau, gain, bias, W, mask, E, D, out);
}

// round 4
// speedup vs baseline: 1.6450x; 1.2015x over previous
#include <cuda_runtime.h>
#include <cstdint>

#define DT_F      0.1f
#define NITERS    9               // int(1.0 // 0.1) == 9 in Python float semantics!
#define BATCH     64
#define NN        1024
#define NOBS      64
#define NACT      16
#define GROUPS    4
#define CPB       32              // CTAs per batch
#define NROWS     32              // rows per CTA
#define BPG       (BATCH / GROUPS)   // 16 batches per group
#define PAIRS     (BPG / 2)          // 8 pairs, interleaved A/B
#define NTHREADS  256

// y-exchange buffer: 8-byte words = (tag<<32) | float_bits. Double buffered by iter parity.
__device__ unsigned long long g_ybuf[2][BATCH][NN];

__device__ __forceinline__ unsigned long long ldcg64(const unsigned long long* p) {
    unsigned long long v;
    asm volatile("ld.global.cg.u64 %0, [%1];" : "=l"(v) : "l"(p));
    return v;
}
__device__ __forceinline__ void stcg64(unsigned long long* p, unsigned long long v) {
    asm volatile("st.global.cg.u64 [%0], %1;" :: "l"(p), "l"(v) : "memory");
}

__global__ void ctrnn_init_kernel() {
    int idx = blockIdx.x * blockDim.x + threadIdx.x;
    if (idx < 2 * BATCH * NN)
        ((unsigned long long*)g_ybuf)[idx] = 0ull;
}

// SMEM layout (dynamic):
//   float4 Ws[NROWS*NN/4]  : 131072 B  (W chunk of batch B; also TMA staging for A before reg copy)
//   float  y_sA[NN], y_sB[NN]
//   float  PA[6*NROWS], PB[6*NROWS]   (v, a=dt/tau, I, gain, bias, mask)
//   float  obs_s[NOBS], red_s[8]
//   u64    mbar
#define SMEM_FLOATS (NROWS * NN + 2 * NN + 12 * NROWS + NOBS + 8 + 4)
#define SMEM_BYTES  (SMEM_FLOATS * 4)

__device__ __forceinline__ void mbar_init(uint32_t a, uint32_t cnt) {
    asm volatile("mbarrier.init.shared.b64 [%0], %1;" :: "r"(a), "r"(cnt) : "memory");
}
__device__ __forceinline__ void mbar_expect_tx(uint32_t a, uint32_t bytes) {
    asm volatile("mbarrier.arrive.expect_tx.shared.b64 _, [%0], %1;" :: "r"(a), "r"(bytes) : "memory");
}
__device__ __forceinline__ void mbar_wait(uint32_t a, uint32_t parity) {
    asm volatile(
        "{\n\t.reg .pred P;\n\t"
        "W_%=:\n\t"
        "mbarrier.try_wait.parity.shared.b64 P, [%0], %1;\n\t"
        "@P bra.uni D_%=;\n\t"
        "bra.uni W_%=;\n\t"
        "D_%=:\n\t}"
        :: "r"(a), "r"(parity) : "memory");
}
__device__ __forceinline__ void bulk_g2s(uint32_t dst, const void* src, uint32_t bytes, uint32_t mbar) {
    asm volatile(
        "cp.async.bulk.shared::cta.global.mbarrier::complete_tx::bytes [%0], [%1], %2, [%3];"
        :: "r"(dst), "l"(src), "r"(bytes), "r"(mbar) : "memory");
}

__device__ __forceinline__ void issue_wload(uint32_t WsAddr, const float* W,
                                            int b, int base, uint32_t mbar) {
    asm volatile("fence.proxy.async.shared::cta;" ::: "memory");
    mbar_expect_tx(mbar, NROWS * NN * 4);
    const char* src = (const char*)(W + ((size_t)b * NN + base) * NN);
    #pragma unroll
    for (int c = 0; c < 4; c++)
        bulk_g2s(WsAddr + c * 32768, src + c * 32768, 32768, mbar);
}

// gather 1024 tagged words (MLP=4 polling) into y_s
__device__ __forceinline__ void gather_y(const unsigned long long* src, unsigned exp,
                                         float* y_s, int tid) {
    unsigned long long a0 = ldcg64(src + tid);
    unsigned long long a1 = ldcg64(src + tid + 256);
    unsigned long long a2 = ldcg64(src + tid + 512);
    unsigned long long a3 = ldcg64(src + tid + 768);
    while ((unsigned)(a0 >> 32) != exp) { __nanosleep(20); a0 = ldcg64(src + tid); }
    while ((unsigned)(a1 >> 32) != exp) { __nanosleep(20); a1 = ldcg64(src + tid + 256); }
    while ((unsigned)(a2 >> 32) != exp) { __nanosleep(20); a2 = ldcg64(src + tid + 512); }
    while ((unsigned)(a3 >> 32) != exp) { __nanosleep(20); a3 = ldcg64(src + tid + 768); }
    y_s[tid]       = __uint_as_float((unsigned)(a0 & 0xffffffffu));
    y_s[tid + 256] = __uint_as_float((unsigned)(a1 & 0xffffffffu));
    y_s[tid + 512] = __uint_as_float((unsigned)(a2 & 0xffffffffu));
    y_s[tid + 768] = __uint_as_float((unsigned)(a3 & 0xffffffffu));
}

// prologue for batch b: y0 into y_s, params into P (v,a,I,g,b,m each NROWS)
__device__ __forceinline__ void prologue(int b, int base, int tid,
    const float* __restrict__ obs, const float* __restrict__ v0,
    const float* __restrict__ tau, const float* __restrict__ gain,
    const float* __restrict__ bias, const float* __restrict__ mask,
    const float* __restrict__ E,
    float* y_s, float* P, float* obs_s)
{
    if (tid < NOBS) obs_s[tid] = obs[(size_t)b * NOBS + tid];
    const float* vg = v0   + (size_t)b * NN;
    const float* gg = gain + (size_t)b * NN;
    const float* bg = bias + (size_t)b * NN;
    const float* mg = mask + (size_t)b * NN;
    for (int i = tid; i < NN; i += NTHREADS)
        y_s[i] = tanhf(gg[i] * (vg[i] + bg[i])) * mg[i];
    __syncthreads();   // obs_s + y0 ready
    if (tid < NROWS) {
        int n = base + tid;
        P[0 * NROWS + tid] = vg[n];
        P[1 * NROWS + tid] = DT_F / tau[(size_t)b * NN + n];
        P[3 * NROWS + tid] = gg[n];
        P[4 * NROWS + tid] = bg[n];
        P[5 * NROWS + tid] = mg[n];
        const float* Er = E + ((size_t)b * NN + n) * NOBS;
        float s = 0.f;
        #pragma unroll
        for (int o = 0; o < NOBS; o++) s += Er[o] * obs_s[o];
        P[2 * NROWS + tid] = s;
    }
    __syncthreads();   // params visible; obs_s free for next prologue
}

// decode: this CTA (cig<NACT) produces action 'cig' for batch b, using y_stage as temp
__device__ __forceinline__ void decode(int b, int cig, int tid, int warp, int lane,
                                       const float* __restrict__ D, float* out,
                                       float* y_stage, float* red_s)
{
    gather_y(&g_ybuf[NITERS & 1][b][0], (unsigned)NITERS, y_stage, tid);
    __syncthreads();
    const float* Dr = D + ((size_t)b * NACT + cig) * NN;
    float p = 0.f;
    for (int i = tid; i < NN; i += NTHREADS) p += Dr[i] * y_stage[i];
    #pragma unroll
    for (int off = 16; off > 0; off >>= 1)
        p += __shfl_xor_sync(0xffffffffu, p, off);
    if (lane == 0) red_s[warp] = p;
    __syncthreads();
    if (tid == 0) {
        float s = 0.f;
        #pragma unroll
        for (int j = 0; j < 8; j++) s += red_s[j];
        out[b * NACT + cig] = s;
    }
    __syncthreads();
}

__global__ __launch_bounds__(NTHREADS, 1)
void ctrnn_kernel(const float* __restrict__ obs,  const float* __restrict__ v0,
                  const float* __restrict__ tau,  const float* __restrict__ gain,
                  const float* __restrict__ bias, const float* __restrict__ W,
                  const float* __restrict__ mask, const float* __restrict__ E,
                  const float* __restrict__ D,    float* __restrict__ out)
{
    extern __shared__ float4 sm4[];
    float4* Ws    = sm4;                               // 8192 float4
    float*  y_sA  = (float*)(Ws + NROWS * (NN / 4));   // 1024
    float*  y_sB  = y_sA + NN;                         // 1024
    float*  PA    = y_sB + NN;                         // 6*32
    float*  PB    = PA + 6 * NROWS;                    // 6*32
    float*  obs_s = PB + 6 * NROWS;                    // 64
    float*  red_s = obs_s + NOBS;                      // 8
    unsigned long long* mbar64 = (unsigned long long*)(red_s + 8);

    const int tid  = threadIdx.x;
    const int warp = tid >> 5;
    const int lane = tid & 31;
    const int group = blockIdx.x >> 5;
    const int cig   = blockIdx.x & 31;
    const int base  = cig * NROWS;

    const uint32_t mbar   = (uint32_t)__cvta_generic_to_shared(mbar64);
    const uint32_t WsAddr = (uint32_t)__cvta_generic_to_shared(Ws);

    // kick off W load for pair 0's batch A
    if (tid == 0) {
        mbar_init(mbar, 1);
        asm volatile("fence.proxy.async.shared::cta;" ::: "memory");
        issue_wload(WsAddr, W, group * BPG + 0, base, mbar);
    }
    __syncthreads();

    float4 Wreg[4][8];    // batch A's 4 rows x 8 float4 per lane
    int li = 0;           // mbar load-completion counter (parity = li&1)

    for (int p = 0; p < PAIRS; p++) {
        const int bA = group * BPG + 2 * p;
        const int bB = bA + 1;

        // ---- wait W_A, copy staging -> registers ----
        mbar_wait(mbar, (uint32_t)(li & 1)); li++;
        {
            const float4* Wrow0 = Ws + (size_t)(warp * 4) * (NN / 4);
            #pragma unroll
            for (int r = 0; r < 4; r++)
                #pragma unroll
                for (int j = 0; j < 8; j++)
                    Wreg[r][j] = Wrow0[r * (NN / 4) + j * 32 + lane];
        }
        __syncthreads();   // staging free

        // ---- issue W_B into staging (stays there for the whole pair) ----
        if (tid == 0) issue_wload(WsAddr, W, bB, base, mbar);

        // ---- prologues (overlap W_B flight) ----
        prologue(bA, base, tid, obs, v0, tau, gain, bias, mask, E, y_sA, PA, obs_s);
        prologue(bB, base, tid, obs, v0, tau, gain, bias, mask, E, y_sB, PB, obs_s);

        mbar_wait(mbar, (uint32_t)(li & 1)); li++;   // W_B resident
        __syncthreads();

        const float4* Y4A = (const float4*)y_sA;
        const float4* Y4B = (const float4*)y_sB;

        for (int t = 1; t <= NITERS; t++) {
            // ================= batch A phase (W in registers) =================
            if (t > 1) gather_y(&g_ybuf[(t - 1) & 1][bA][0], (unsigned)(t - 1), y_sA, tid);
            __syncthreads();
            {
                float acc0 = 0.f, acc1 = 0.f, acc2 = 0.f, acc3 = 0.f;
                #pragma unroll
                for (int j = 0; j < 8; j++) {
                    float4 y4 = Y4A[j * 32 + lane];
                    float4 a;
                    a = Wreg[0][j]; acc0 += a.x*y4.x; acc0 += a.y*y4.y; acc0 += a.z*y4.z; acc0 += a.w*y4.w;
                    a = Wreg[1][j]; acc1 += a.x*y4.x; acc1 += a.y*y4.y; acc1 += a.z*y4.z; acc1 += a.w*y4.w;
                    a = Wreg[2][j]; acc2 += a.x*y4.x; acc2 += a.y*y4.y; acc2 += a.z*y4.z; acc2 += a.w*y4.w;
                    a = Wreg[3][j]; acc3 += a.x*y4.x; acc3 += a.y*y4.y; acc3 += a.z*y4.z; acc3 += a.w*y4.w;
                }
                #pragma unroll
                for (int off = 16; off > 0; off >>= 1) {
                    acc0 += __shfl_xor_sync(0xffffffffu, acc0, off);
                    acc1 += __shfl_xor_sync(0xffffffffu, acc1, off);
                    acc2 += __shfl_xor_sync(0xffffffffu, acc2, off);
                    acc3 += __shfl_xor_sync(0xffffffffu, acc3, off);
                }
                if (lane < 4) {
                    float dot = (lane == 0) ? acc0 : (lane == 1) ? acc1 : (lane == 2) ? acc2 : acc3;
                    int r = warp * 4 + lane;
                    float v  = PA[0 * NROWS + r];
                    float nv = (v + PA[1 * NROWS + r] * (dot + PA[2 * NROWS + r] - v)) * PA[5 * NROWS + r];
                    PA[0 * NROWS + r] = nv;
                    float ov = (t < NITERS)
                        ? tanhf(PA[3 * NROWS + r] * (nv + PA[4 * NROWS + r])) * PA[5 * NROWS + r]
                        : nv;
                    unsigned long long pk =
                        ((unsigned long long)(unsigned)t << 32) |
                        (unsigned long long)__float_as_uint(ov);
                    stcg64(&g_ybuf[t & 1][bA][base + r], pk);
                }
            }

            // ================= batch B phase (W in SMEM) =================
            if (t > 1) gather_y(&g_ybuf[(t - 1) & 1][bB][0], (unsigned)(t - 1), y_sB, tid);
            __syncthreads();
            {
                float acc0 = 0.f, acc1 = 0.f, acc2 = 0.f, acc3 = 0.f;
                const float4* W0 = Ws + (size_t)(warp * 4 + 0) * (NN / 4);
                const float4* W1 = W0 + (NN / 4);
                const float4* W2 = W1 + (NN / 4);
                const float4* W3 = W2 + (NN / 4);
                #pragma unroll
                for (int k = 0; k < 8; k++) {
                    int c = k * 32 + lane;
                    float4 y4 = Y4B[c];
                    float4 a;
                    a = W0[c]; acc0 += a.x*y4.x; acc0 += a.y*y4.y; acc0 += a.z*y4.z; acc0 += a.w*y4.w;
                    a = W1[c]; acc1 += a.x*y4.x; acc1 += a.y*y4.y; acc1 += a.z*y4.z; acc1 += a.w*y4.w;
                    a = W2[c]; acc2 += a.x*y4.x; acc2 += a.y*y4.y; acc2 += a.z*y4.z; acc2 += a.w*y4.w;
                    a = W3[c]; acc3 += a.x*y4.x; acc3 += a.y*y4.y; acc3 += a.z*y4.z; acc3 += a.w*y4.w;
                }
                #pragma unroll
                for (int off = 16; off > 0; off >>= 1) {
                    acc0 += __shfl_xor_sync(0xffffffffu, acc0, off);
                    acc1 += __shfl_xor_sync(0xffffffffu, acc1, off);
                    acc2 += __shfl_xor_sync(0xffffffffu, acc2, off);
                    acc3 += __shfl_xor_sync(0xffffffffu, acc3, off);
                }
                if (lane < 4) {
                    float dot = (lane == 0) ? acc0 : (lane == 1) ? acc1 : (lane == 2) ? acc2 : acc3;
                    int r = warp * 4 + lane;
                    float v  = PB[0 * NROWS + r];
                    float nv = (v + PB[1 * NROWS + r] * (dot + PB[2 * NROWS + r] - v)) * PB[5 * NROWS + r];
                    PB[0 * NROWS + r] = nv;
                    float ov = (t < NITERS)
                        ? tanhf(PB[3 * NROWS + r] * (nv + PB[4 * NROWS + r])) * PB[5 * NROWS + r]
                        : nv;
                    unsigned long long pk =
                        ((unsigned long long)(unsigned)t << 32) |
                        (unsigned long long)__float_as_uint(ov);
                    stcg64(&g_ybuf[t & 1][bB][base + r], pk);
                }
            }
        }
        __syncthreads();   // all threads done reading Ws (W_B) and y buffers

        // ---- prefetch next pair's W_A into staging (overlaps decode) ----
        if (tid == 0 && p + 1 < PAIRS) issue_wload(WsAddr, W, bA + 2, base, mbar);

        // ---- decode: CTAs 0..15 each produce one action for both batches ----
        if (cig < NACT) {
            decode(bA, cig, tid, warp, lane, D, out, y_sA, red_s);
            decode(bB, cig, tid, warp, lane, D, out, y_sA, red_s);
        }
        __syncthreads();
    }
}

extern "C" void kernel_launch(void* const* d_in, const int* in_sizes, int n_in,
                              void* d_out, int out_size) {
    const float* obs  = (const float*)d_in[0];
    const float* v0   = (const float*)d_in[1];
    const float* tau  = (const float*)d_in[2];
    const float* gain = (const float*)d_in[3];
    const float* bias = (const float*)d_in[4];
    const float* W    = (const float*)d_in[5];
    const float* mask = (const float*)d_in[6];
    const float* E    = (const float*)d_in[7];
    const float* D    = (const float*)d_in[8];
    float* out = (float*)d_out;

    cudaFuncSetAttribute(ctrnn_kernel,
                         cudaFuncAttributeMaxDynamicSharedMemorySize, SMEM_BYTES);

    // reset exchange tags each launch (graph-replay safe, deterministic)
    ctrnn_init_kernel<<<(2 * BATCH * NN + 255) / 256, 256>>>();

    // 128 CTAs, ~141 KB smem each -> 1 CTA/SM, all co-resident on 148 SMs
    ctrnn_kernel<<<GROUPS * CPB, NTHREADS, SMEM_BYTES>>>(
        obs, v0, tau, gain, bias, W, mask, E, D, out);
}